// round 15
// baseline (speedup 1.0000x reference)
#include <cuda_runtime.h>
#include <cuda_bf16.h>
#include <cstdint>

#define T_FRAMES 16384
#define E_DIM    1024
#define M_MODELS 8
#define K_CLUST  512

#define TM   64
#define TN   512
#define KBLK 128
#define NSTAGE (E_DIM / KBLK)   // 8
#define MAXT_G 34               // grid tiles per model (stride loop guards overflow)
#define NTHREADS 1024
#define TAU  20.0f
#define CAP  4096

#define B_STAGE_BYTES 65536

// ---- persistent scratch ----
__device__ uint8_t g_cent_s8[M_MODELS * NSTAGE * B_STAGE_BYTES];   // 4.2MB
__device__ int   g_counts[M_MODELS];
__device__ int   g_rows[M_MODELS * T_FRAMES];
__device__ float g_chalf[M_MODELS * K_CLUST];

// ================= helpers =================
__device__ __forceinline__ uint32_t smem_u32(const void* p) {
    uint32_t a;
    asm("{ .reg .u64 t; cvta.to.shared.u64 t, %1; cvt.u32.u64 %0, t; }" : "=r"(a) : "l"(p));
    return a;
}
__device__ __forceinline__ void bulk_g2s(uint32_t dst, const void* src,
                                         uint32_t bytes, uint32_t mbar) {
    asm volatile(
        "cp.async.bulk.shared::cluster.global.mbarrier::complete_tx::bytes [%0], [%1], %2, [%3];"
        :: "r"(dst), "l"(src), "r"(bytes), "r"(mbar) : "memory");
}
#define MBARRIER_INIT(addr, cnt) \
    asm volatile("mbarrier.init.shared.b64 [%0], %1;" :: "r"((uint32_t)(addr)), "r"((uint32_t)(cnt)) : "memory")
#define MBARRIER_EXPECT_TX(addr, bytes) \
    asm volatile("mbarrier.arrive.expect_tx.shared.b64 _, [%0], %1;" \
                 :: "r"((uint32_t)(addr)), "r"((uint32_t)(bytes)) : "memory")
#define MBARRIER_WAIT_PARITY(addr, par) do { \
    uint32_t _mb = (uint32_t)(addr); uint32_t _pr = (uint32_t)(par); uint32_t _done; \
    asm volatile("{\n\t.reg .pred p;\n\t" \
        "mbarrier.try_wait.parity.acquire.cta.shared::cta.b64 p, [%1], %2;\n\t" \
        "selp.b32 %0, 1, 0, p;\n\t}" : "=r"(_done) : "r"(_mb), "r"(_pr) : "memory"); \
    if (!_done) { \
        asm volatile("{\n\t.reg .pred P1;\n\t" \
            "WL_%=:\n\t" \
            "mbarrier.try_wait.parity.acquire.cta.shared::cta.b64 P1, [%0], %1, 0x989680;\n\t" \
            "@P1 bra.uni WD_%=;\n\t" \
            "bra.uni WL_%=;\n\t" \
            "WD_%=:\n\t}" :: "r"(_mb), "r"(_pr) : "memory"); \
    } } while (0)
__device__ __forceinline__ void ldmx4(uint32_t addr, uint32_t& r0, uint32_t& r1,
                                      uint32_t& r2, uint32_t& r3) {
    asm volatile("ldmatrix.sync.aligned.m8n8.x4.shared.b16 {%0,%1,%2,%3}, [%4];"
                 : "=r"(r0), "=r"(r1), "=r"(r2), "=r"(r3) : "r"(addr));
}
__device__ __forceinline__ void mma_fp8(float* c, uint32_t a0, uint32_t a1,
                                        uint32_t a2, uint32_t a3,
                                        uint32_t b0, uint32_t b1) {
    asm volatile(
        "mma.sync.aligned.m16n8k32.row.col.f32.e4m3.e4m3.f32 "
        "{%0,%1,%2,%3}, {%4,%5,%6,%7}, {%8,%9}, {%0,%1,%2,%3};"
        : "+f"(c[0]), "+f"(c[1]), "+f"(c[2]), "+f"(c[3])
        : "r"(a0), "r"(a1), "r"(a2), "r"(a3), "r"(b0), "r"(b1));
}
__device__ __forceinline__ unsigned int fkey(float f) {
    unsigned u = __float_as_uint(f);
    return (u & 0x80000000u) ? ~u : (u | 0x80000000u);
}
__device__ __forceinline__ uint32_t f4_to_fp8(float4 v) {
    uint32_t p;
    asm("{ .reg .b16 lo, hi;\n\t"
        "cvt.rn.satfinite.e4m3x2.f32 lo, %2, %1;\n\t"
        "cvt.rn.satfinite.e4m3x2.f32 hi, %4, %3;\n\t"
        "mov.b32 %0, {lo, hi}; }"
        : "=r"(p) : "f"(v.x), "f"(v.y), "f"(v.z), "f"(v.w));
    return p;
}

// ================= smem layout (bytes) =================
#define SM_B      0                        // 2 x 64KB
#define SM_A      131072                   // 2 x 8KB
#define SM_CHALF  147456                   // 512 f32
#define SM_ROWIDX 149504                   // 64 int
#define SM_THR    149760                   // 64 f32
#define SM_PMIN   150016                   // 64 x 8 f32
#define SM_BEST   152064                   // 64 u64
#define SM_MBAR   152576                   // 2 x 8B
#define SM_CNT    152592                   // int (+pad)
#define SM_CODE   152608                   // 64 int
#define SM_CAND   152864                   // CAP ints
#define SMEM_TOTAL (152864 + CAP * 4 + 32) // ~169KB -> 1 CTA/SM

// ================= prep: cent pack/chalf (all blocks) + bucketing (block 0) =================
// grid = 512 blocks x 256 threads (one warp per centroid row)
__global__ void prep_kernel(const float* __restrict__ cent,
                            const int* __restrict__ model_idx) {
    __shared__ int hist[256][8];   // block-0 counting sort state

    int gt = blockIdx.x * blockDim.x + threadIdx.x;
    int warp = gt >> 5;                    // 0 .. 4095 == M*K-1 (exact)
    int lane = threadIdx.x & 31;
    {
        const int m = warp >> 9;
        const int r = warp & 511;
        const float4* src = reinterpret_cast<const float4*>(cent + (size_t)warp * E_DIM);
        uint8_t* base = g_cent_s8 + (size_t)m * NSTAGE * B_STAGE_BYTES;
        const uint32_t sw16 = ((lane >> 2) ^ (r & 7)) << 4;
        const uint32_t boff = (lane & 3) * 4;
        float s = 0.f;
        #pragma unroll
        for (int q = 0; q < 8; ++q) {
            float4 v = src[lane + 32 * q];
            *reinterpret_cast<uint32_t*>(base + q * B_STAGE_BYTES + r * 128 + sw16 + boff)
                = f4_to_fp8(v);
            s += v.x * v.x + v.y * v.y + v.z * v.z + v.w * v.w;
        }
        #pragma unroll
        for (int o = 16; o; o >>= 1) s += __shfl_xor_sync(0xffffffffu, s, o);
        if (lane == 0) g_chalf[warp] = 0.5f * s;
    }

    // ---- block 0: deterministic bucketing (counting sort, no global init) ----
    if (blockIdx.x == 0) {
        const int t0 = threadIdx.x;          // 256 threads, 64 frames each
        #pragma unroll
        for (int mm = 0; mm < 8; ++mm) hist[t0][mm] = 0;
        __syncthreads();
        for (int i = 0; i < 64; ++i)
            hist[t0][model_idx[t0 * 64 + i]]++;
        __syncthreads();
        if (t0 < 8) {                        // exclusive scan over 256 chunks, per model
            int s = 0;
            for (int j = 0; j < 256; ++j) { int v = hist[j][t0]; hist[j][t0] = s; s += v; }
            g_counts[t0] = s;
        }
        __syncthreads();
        for (int i = 0; i < 64; ++i) {       // stable scatter (frame-ordered)
            int f = t0 * 64 + i;
            int mm = model_idx[f];
            g_rows[mm * T_FRAMES + hist[t0][mm]++] = f;
        }
    }

    // PDL: signal dependents once this block's stores are issued
    asm volatile("griddepcontrol.launch_dependents;" ::: "memory");
}

// ================= fused GEMM + argmin + rescore + output =================
// grid.x = M_MODELS * MAXT_G : m = bx / MAXT_G, tile-stride loop over mt
__global__ __launch_bounds__(NTHREADS, 1)
void fused_kernel(const float* __restrict__ emb, const float* __restrict__ cent,
                  float* __restrict__ out) {
    // PDL: wait for prep's writes before touching g_counts/g_rows/g_chalf/g_cent_s8
    asm volatile("griddepcontrol.wait;" ::: "memory");

    extern __shared__ char smem[];
    const uint32_t sb = smem_u32(smem);

    const int m   = blockIdx.x / MAXT_G;
    const int mtb = blockIdx.x % MAXT_G;
    const int cnt = g_counts[m];
    const int ntiles = (cnt + TM - 1) / TM;
    const int* rowsm = g_rows + m * T_FRAMES;

    const int tid  = threadIdx.x;
    const int wid  = tid >> 5;
    const int lane = tid & 31;
    const int wr = wid >> 3;      // 0..3 : 16-frame row group
    const int wc = wid & 7;       // 0..7 : 64-centroid col group

    int*   rowidx_s = reinterpret_cast<int*>(smem + SM_ROWIDX);
    float* chalf_s  = reinterpret_cast<float*>(smem + SM_CHALF);
    float* thr_s    = reinterpret_cast<float*>(smem + SM_THR);
    float* pmin_s   = reinterpret_cast<float*>(smem + SM_PMIN);
    unsigned long long* best_s = reinterpret_cast<unsigned long long*>(smem + SM_BEST);
    int* cnt_s  = reinterpret_cast<int*>(smem + SM_CNT);
    int* code_s = reinterpret_cast<int*>(smem + SM_CODE);
    int* cand_s = reinterpret_cast<int*>(smem + SM_CAND);

    if (tid < TN) chalf_s[tid] = g_chalf[m * K_CLUST + tid];
    if (tid == 0) {
        MBARRIER_INIT(sb + SM_MBAR, 1);
        MBARRIER_INIT(sb + SM_MBAR + 8, 1);
    }
    __syncthreads();

    const uint8_t* bsrc = g_cent_s8 + (size_t)m * NSTAGE * B_STAGE_BYTES;
    const float4* emb4  = reinterpret_cast<const float4*>(emb);
    const float4* cent4 = reinterpret_cast<const float4*>(cent);

    const int ar = tid >> 4, af = tid & 15;
    const uint32_t ad = ar * 128 + (((af >> 1) ^ (ar & 7)) << 4) + (af & 1) * 8;
    const int arow_l = wr * 16 + (lane & 7) + ((lane >> 3) & 1) * 8;
    const int brow_l = wc * 64 + (lane & 7) + ((lane >> 3) & 1) * 8;
    const int clane  = lane >> 4;
    const int gid = lane >> 2, tig = lane & 3;

    uint32_t par[2] = {0, 0};

    for (int mt = mtb; mt < ntiles; mt += MAXT_G) {
        __syncthreads();   // previous tile's epilogue readers done
        if (tid < TM) {
            int gr = mt * TM + tid;
            rowidx_s[tid] = rowsm[min(gr, cnt - 1)];
            best_s[tid] = 0xFFFFFFFFFFFFFFFFull;
        }
        if (tid == 0) cnt_s[0] = 0;
        __syncthreads();

        const float4* aS = emb4 + (size_t)rowidx_s[ar] * 256 + af * 2;

        float acc[8][4];
        #pragma unroll
        for (int n = 0; n < 8; ++n)
            #pragma unroll
            for (int r = 0; r < 4; ++r) acc[n][r] = 0.f;

        // prologue: stage-0 B bulk + stage-0 A regs
        if (tid == 0) {
            MBARRIER_EXPECT_TX(sb + SM_MBAR, B_STAGE_BYTES);
            bulk_g2s(sb + SM_B, bsrc, B_STAGE_BYTES, sb + SM_MBAR);
        }
        float4 apre0 = aS[0], apre1 = aS[1];

        for (int kb = 0; kb < NSTAGE; ++kb) {
            const int buf = kb & 1;
            const uint32_t Ab = sb + SM_A + buf * 8192;
            const uint32_t Bb = sb + SM_B + buf * 65536;
            // store current A stage (prev readers of this A buffer drained at BAR(kb-1))
            *reinterpret_cast<uint2*>(smem + SM_A + buf * 8192 + ad) =
                make_uint2(f4_to_fp8(apre0), f4_to_fp8(apre1));
            if (kb + 1 < NSTAGE) {
                apre0 = aS[(kb + 1) * 32];
                apre1 = aS[(kb + 1) * 32 + 1];
            }
            // wait current B, single barrier, then refill the drained buffer
            if (buf == 0) { MBARRIER_WAIT_PARITY(sb + SM_MBAR, par[0]); par[0] ^= 1; }
            else          { MBARRIER_WAIT_PARITY(sb + SM_MBAR + 8, par[1]); par[1] ^= 1; }
            __syncthreads();
            if (kb + 1 < NSTAGE && tid == 0) {
                const int nb = (kb + 1) & 1;
                MBARRIER_EXPECT_TX(sb + SM_MBAR + 8 * nb, B_STAGE_BYTES);
                bulk_g2s(sb + SM_B + nb * 65536, bsrc + (kb + 1) * B_STAGE_BYTES,
                         B_STAGE_BYTES, sb + SM_MBAR + 8 * nb);
            }

            #pragma unroll
            for (int ks = 0; ks < 4; ++ks) {      // k32 slice within 128-fp8 stage
                const int cc = ks * 2 + clane;
                uint32_t a0, a1, a2, a3;
                ldmx4(Ab + arow_l * 128 + ((cc ^ (arow_l & 7)) << 4), a0, a1, a2, a3);
                #pragma unroll
                for (int nh = 0; nh < 2; ++nh) {
                    uint32_t b[2][4];
                    #pragma unroll
                    for (int nj = 0; nj < 2; ++nj) {
                        int row = brow_l + nh * 32 + nj * 16;
                        ldmx4(Bb + row * 128 + ((cc ^ (row & 7)) << 4),
                              b[nj][0], b[nj][1], b[nj][2], b[nj][3]);
                    }
                    #pragma unroll
                    for (int n = 0; n < 4; ++n)
                        mma_fp8(acc[nh * 4 + n], a0, a1, a2, a3,
                                b[n >> 1][n & 1], b[n >> 1][2 + (n & 1)]);
                }
            }
        }

        // ---- epilogue 1: per-row approx min over this warp's 64 cols ----
        {
            float v0 = __int_as_float(0x7F800000), v1 = v0;
            #pragma unroll
            for (int n = 0; n < 8; ++n) {
                int col = wc * 64 + n * 8 + tig * 2;
                float c0 = chalf_s[col], c1 = chalf_s[col + 1];
                v0 = fminf(v0, fminf(c0 - acc[n][0], c1 - acc[n][1]));
                v1 = fminf(v1, fminf(c0 - acc[n][2], c1 - acc[n][3]));
            }
            #pragma unroll
            for (int o = 1; o < 4; o <<= 1) {
                v0 = fminf(v0, __shfl_xor_sync(0xffffffffu, v0, o));
                v1 = fminf(v1, __shfl_xor_sync(0xffffffffu, v1, o));
            }
            if (tig == 0) {
                pmin_s[(wr * 16 + gid) * 8 + wc] = v0;
                pmin_s[(wr * 16 + gid + 8) * 8 + wc] = v1;
            }
        }
        __syncthreads();
        if (tid < TM) {
            float v = pmin_s[tid * 8];
            #pragma unroll
            for (int w = 1; w < 8; ++w) v = fminf(v, pmin_s[tid * 8 + w]);
            thr_s[tid] = v + TAU;
        }
        __syncthreads();

        // ---- epilogue 2: collect candidates ----
        #pragma unroll
        for (int n = 0; n < 8; ++n) {
            #pragma unroll
            for (int r = 0; r < 4; ++r) {
                int row = wr * 16 + gid + (r >> 1) * 8;
                int col = wc * 64 + n * 8 + tig * 2 + (r & 1);
                float s = chalf_s[col] - acc[n][r];
                if (s <= thr_s[row]) {
                    int idx = atomicAdd(cnt_s, 1);
                    if (idx < CAP) cand_s[idx] = (row << 16) | col;
                }
            }
        }
        __syncthreads();
        const int ncand = min(cnt_s[0], CAP);

        // ---- epilogue 3: exact fp32 rescore (one warp per candidate) ----
        for (int i = wid; i < ncand; i += 32) {
            int rc = cand_s[i];
            int row = rc >> 16, col = rc & 0xFFFF;
            const float4* e4 = emb4 + (size_t)rowidx_s[row] * 256;
            const float4* c4 = cent4 + ((size_t)m * K_CLUST + col) * 256;
            float d = 0.f;
            #pragma unroll
            for (int q = 0; q < 8; ++q) {
                float4 ea = e4[q * 32 + lane];
                float4 ca = c4[q * 32 + lane];
                d += ea.x * ca.x + ea.y * ca.y + ea.z * ca.z + ea.w * ca.w;
            }
            #pragma unroll
            for (int o = 16; o; o >>= 1) d += __shfl_xor_sync(0xffffffffu, d, o);
            if (lane == 0) {
                float s = chalf_s[col] - d;   // exact fp32 score
                unsigned long long key = ((unsigned long long)fkey(s) << 32) | (unsigned)col;
                atomicMin(&best_s[row], key); // ties -> smaller col (first-min)
            }
        }
        __syncthreads();
        if (tid < TM) code_s[tid] = (int)(unsigned)(best_s[tid] & 0xFFFFFFFFull);
        __syncthreads();

        // ---- epilogue 4: write output rows directly ----
        float4* out4 = reinterpret_cast<float4*>(out);
        for (int idx = tid; idx < TM * 256; idx += NTHREADS) {
            int r = idx >> 8, q = idx & 255;
            if (mt * TM + r < cnt) {
                int frame = rowidx_s[r];
                out4[(size_t)frame * 256 + q] =
                    cent4[((size_t)m * K_CLUST + code_s[r]) * 256 + q];
            }
        }
    }
}

// ================= launch =================
extern "C" void kernel_launch(void* const* d_in, const int* in_sizes, int n_in,
                              void* d_out, int out_size) {
    const float* emb  = (const float*)d_in[0];
    const float* cent = (const float*)d_in[1];
    const int*   midx = (const int*)d_in[2];
    float* out = (float*)d_out;

    cudaFuncSetAttribute(fused_kernel,
                         cudaFuncAttributeMaxDynamicSharedMemorySize, SMEM_TOTAL);

    prep_kernel<<<(M_MODELS * K_CLUST * 32) / 256, 256>>>(cent, midx);

    // fused launch with programmatic dependent launch (overlaps prep tail)
    cudaLaunchConfig_t cfg = {};
    cfg.gridDim = dim3(M_MODELS * MAXT_G);
    cfg.blockDim = dim3(NTHREADS);
    cfg.dynamicSmemBytes = SMEM_TOTAL;
    cfg.stream = 0;
    cudaLaunchAttribute at[1];
    at[0].id = cudaLaunchAttributeProgrammaticStreamSerialization;
    at[0].val.programmaticStreamSerializationAllowed = 1;
    cfg.attrs = at;
    cfg.numAttrs = 1;
    cudaLaunchKernelEx(&cfg, fused_kernel, emb, cent, out);
}

// round 16
// speedup vs baseline: 1.1764x; 1.1764x over previous
#include <cuda_runtime.h>
#include <cuda_bf16.h>
#include <cstdint>

#define T_FRAMES 16384
#define E_DIM    1024
#define M_MODELS 8
#define K_CLUST  512

#define TM   64
#define TN   512
#define KBLK 128
#define NSTAGE (E_DIM / KBLK)   // 8
#define MAXT_G 34               // grid tiles per model (stride loop guards overflow)
#define NTHREADS 1024
#define TAU  20.0f
#define CAP  4096

#define B_STAGE_BYTES 65536

// ---- persistent scratch ----
__device__ uint8_t g_cent_s8[M_MODELS * NSTAGE * B_STAGE_BYTES];   // 4.2MB
__device__ int   g_counts[M_MODELS];     // zero at load; re-zeroed by fused's last block
__device__ int   g_done;                 // grid arrival counter (self-resetting)
__device__ int   g_rows[M_MODELS * T_FRAMES];
__device__ float g_chalf[M_MODELS * K_CLUST];

// ================= helpers =================
__device__ __forceinline__ uint32_t smem_u32(const void* p) {
    uint32_t a;
    asm("{ .reg .u64 t; cvta.to.shared.u64 t, %1; cvt.u32.u64 %0, t; }" : "=r"(a) : "l"(p));
    return a;
}
__device__ __forceinline__ void bulk_g2s(uint32_t dst, const void* src,
                                         uint32_t bytes, uint32_t mbar) {
    asm volatile(
        "cp.async.bulk.shared::cluster.global.mbarrier::complete_tx::bytes [%0], [%1], %2, [%3];"
        :: "r"(dst), "l"(src), "r"(bytes), "r"(mbar) : "memory");
}
#define MBARRIER_INIT(addr, cnt) \
    asm volatile("mbarrier.init.shared.b64 [%0], %1;" :: "r"((uint32_t)(addr)), "r"((uint32_t)(cnt)) : "memory")
#define MBARRIER_EXPECT_TX(addr, bytes) \
    asm volatile("mbarrier.arrive.expect_tx.shared.b64 _, [%0], %1;" \
                 :: "r"((uint32_t)(addr)), "r"((uint32_t)(bytes)) : "memory")
#define MBARRIER_WAIT_PARITY(addr, par) do { \
    uint32_t _mb = (uint32_t)(addr); uint32_t _pr = (uint32_t)(par); uint32_t _done; \
    asm volatile("{\n\t.reg .pred p;\n\t" \
        "mbarrier.try_wait.parity.acquire.cta.shared::cta.b64 p, [%1], %2;\n\t" \
        "selp.b32 %0, 1, 0, p;\n\t}" : "=r"(_done) : "r"(_mb), "r"(_pr) : "memory"); \
    if (!_done) { \
        asm volatile("{\n\t.reg .pred P1;\n\t" \
            "WL_%=:\n\t" \
            "mbarrier.try_wait.parity.acquire.cta.shared::cta.b64 P1, [%0], %1, 0x989680;\n\t" \
            "@P1 bra.uni WD_%=;\n\t" \
            "bra.uni WL_%=;\n\t" \
            "WD_%=:\n\t}" :: "r"(_mb), "r"(_pr) : "memory"); \
    } } while (0)
__device__ __forceinline__ void ldmx4(uint32_t addr, uint32_t& r0, uint32_t& r1,
                                      uint32_t& r2, uint32_t& r3) {
    asm volatile("ldmatrix.sync.aligned.m8n8.x4.shared.b16 {%0,%1,%2,%3}, [%4];"
                 : "=r"(r0), "=r"(r1), "=r"(r2), "=r"(r3) : "r"(addr));
}
__device__ __forceinline__ void mma_fp8(float* c, uint32_t a0, uint32_t a1,
                                        uint32_t a2, uint32_t a3,
                                        uint32_t b0, uint32_t b1) {
    asm volatile(
        "mma.sync.aligned.m16n8k32.row.col.f32.e4m3.e4m3.f32 "
        "{%0,%1,%2,%3}, {%4,%5,%6,%7}, {%8,%9}, {%0,%1,%2,%3};"
        : "+f"(c[0]), "+f"(c[1]), "+f"(c[2]), "+f"(c[3])
        : "r"(a0), "r"(a1), "r"(a2), "r"(a3), "r"(b0), "r"(b1));
}
__device__ __forceinline__ unsigned int fkey(float f) {
    unsigned u = __float_as_uint(f);
    return (u & 0x80000000u) ? ~u : (u | 0x80000000u);
}
__device__ __forceinline__ uint32_t f4_to_fp8(float4 v) {
    uint32_t p;
    asm("{ .reg .b16 lo, hi;\n\t"
        "cvt.rn.satfinite.e4m3x2.f32 lo, %2, %1;\n\t"
        "cvt.rn.satfinite.e4m3x2.f32 hi, %4, %3;\n\t"
        "mov.b32 %0, {lo, hi}; }"
        : "=r"(p) : "f"(v.x), "f"(v.y), "f"(v.z), "f"(v.w));
    return p;
}

// ================= smem layout (bytes) =================
#define SM_B      0                        // 2 x 64KB
#define SM_A      131072                   // 2 x 8KB
#define SM_CHALF  147456                   // 512 f32
#define SM_ROWIDX 149504                   // 64 int
#define SM_THR    149760                   // 64 f32
#define SM_PMIN   150016                   // 64 x 8 f32
#define SM_BEST   152064                   // 64 u64
#define SM_MBAR   152576                   // 2 x 8B
#define SM_CNT    152592                   // int (+pad)
#define SM_CODE   152608                   // 64 int
#define SM_CAND   152864                   // CAP ints
#define SMEM_TOTAL (152864 + CAP * 4 + 32) // ~169KB -> 1 CTA/SM

// ================= prep: bucket (first 16384 threads) + cent pack/chalf =================
// g_counts guaranteed zero here (module load on first call; fused's last block after).
__global__ void prep_kernel(const float* __restrict__ cent,
                            const int* __restrict__ model_idx) {
    int gt = blockIdx.x * blockDim.x + threadIdx.x;
    if (gt < T_FRAMES) {
        int mm = model_idx[gt];
        int pos = atomicAdd(&g_counts[mm], 1);
        g_rows[mm * T_FRAMES + pos] = gt;
    }
    int warp = gt >> 5;
    int lane = threadIdx.x & 31;
    if (warp < M_MODELS * K_CLUST) {
        const int m = warp >> 9;
        const int r = warp & 511;
        const float4* src = reinterpret_cast<const float4*>(cent + (size_t)warp * E_DIM);
        uint8_t* base = g_cent_s8 + (size_t)m * NSTAGE * B_STAGE_BYTES;
        const uint32_t sw16 = ((lane >> 2) ^ (r & 7)) << 4;
        const uint32_t boff = (lane & 3) * 4;
        float s = 0.f;
        #pragma unroll
        for (int q = 0; q < 8; ++q) {
            float4 v = src[lane + 32 * q];
            *reinterpret_cast<uint32_t*>(base + q * B_STAGE_BYTES + r * 128 + sw16 + boff)
                = f4_to_fp8(v);
            s += v.x * v.x + v.y * v.y + v.z * v.z + v.w * v.w;
        }
        #pragma unroll
        for (int o = 16; o; o >>= 1) s += __shfl_xor_sync(0xffffffffu, s, o);
        if (lane == 0) g_chalf[warp] = 0.5f * s;
    }
    // PDL: allow dependent grid once this block's stores are issued
    asm volatile("griddepcontrol.launch_dependents;" ::: "memory");
}

// ================= fused GEMM + argmin + rescore + output =================
// grid.x = M_MODELS * MAXT_G : m = bx / MAXT_G, tile-stride loop over mt
__global__ __launch_bounds__(NTHREADS, 1)
void fused_kernel(const float* __restrict__ emb, const float* __restrict__ cent,
                  float* __restrict__ out) {
    // PDL: wait for prep's writes before touching its outputs
    asm volatile("griddepcontrol.wait;" ::: "memory");

    extern __shared__ char smem[];
    const uint32_t sb = smem_u32(smem);

    const int m   = blockIdx.x / MAXT_G;
    const int mtb = blockIdx.x % MAXT_G;
    const int cnt = g_counts[m];
    const int ntiles = (cnt + TM - 1) / TM;
    const int* rowsm = g_rows + m * T_FRAMES;

    const int tid  = threadIdx.x;
    const int wid  = tid >> 5;
    const int lane = tid & 31;
    const int wr = wid >> 3;      // 0..3 : 16-frame row group
    const int wc = wid & 7;       // 0..7 : 64-centroid col group

    int*   rowidx_s = reinterpret_cast<int*>(smem + SM_ROWIDX);
    float* chalf_s  = reinterpret_cast<float*>(smem + SM_CHALF);
    float* thr_s    = reinterpret_cast<float*>(smem + SM_THR);
    float* pmin_s   = reinterpret_cast<float*>(smem + SM_PMIN);
    unsigned long long* best_s = reinterpret_cast<unsigned long long*>(smem + SM_BEST);
    int* cnt_s  = reinterpret_cast<int*>(smem + SM_CNT);
    int* code_s = reinterpret_cast<int*>(smem + SM_CODE);
    int* cand_s = reinterpret_cast<int*>(smem + SM_CAND);

    if (tid < TN) chalf_s[tid] = g_chalf[m * K_CLUST + tid];
    if (tid == 0) {
        MBARRIER_INIT(sb + SM_MBAR, 1);
        MBARRIER_INIT(sb + SM_MBAR + 8, 1);
    }
    __syncthreads();

    const uint8_t* bsrc = g_cent_s8 + (size_t)m * NSTAGE * B_STAGE_BYTES;
    const float4* emb4  = reinterpret_cast<const float4*>(emb);
    const float4* cent4 = reinterpret_cast<const float4*>(cent);

    const int ar = tid >> 4, af = tid & 15;
    const uint32_t ad = ar * 128 + (((af >> 1) ^ (ar & 7)) << 4) + (af & 1) * 8;
    const int arow_l = wr * 16 + (lane & 7) + ((lane >> 3) & 1) * 8;
    const int brow_l = wc * 64 + (lane & 7) + ((lane >> 3) & 1) * 8;
    const int clane  = lane >> 4;
    const int gid = lane >> 2, tig = lane & 3;

    uint32_t par[2] = {0, 0};

    for (int mt = mtb; mt < ntiles; mt += MAXT_G) {
        __syncthreads();   // previous tile's epilogue readers done
        if (tid < TM) {
            int gr = mt * TM + tid;
            rowidx_s[tid] = rowsm[min(gr, cnt - 1)];
            best_s[tid] = 0xFFFFFFFFFFFFFFFFull;
        }
        if (tid == 0) cnt_s[0] = 0;
        __syncthreads();

        const float4* aS = emb4 + (size_t)rowidx_s[ar] * 256 + af * 2;

        float acc[8][4];
        #pragma unroll
        for (int n = 0; n < 8; ++n)
            #pragma unroll
            for (int r = 0; r < 4; ++r) acc[n][r] = 0.f;

        // prologue: stage-0 B bulk + stage-0 A regs
        if (tid == 0) {
            MBARRIER_EXPECT_TX(sb + SM_MBAR, B_STAGE_BYTES);
            bulk_g2s(sb + SM_B, bsrc, B_STAGE_BYTES, sb + SM_MBAR);
        }
        float4 apre0 = aS[0], apre1 = aS[1];

        for (int kb = 0; kb < NSTAGE; ++kb) {
            const int buf = kb & 1;
            const uint32_t Ab = sb + SM_A + buf * 8192;
            const uint32_t Bb = sb + SM_B + buf * 65536;
            // store current A stage (prev readers of this A buffer drained at BAR(kb-1))
            *reinterpret_cast<uint2*>(smem + SM_A + buf * 8192 + ad) =
                make_uint2(f4_to_fp8(apre0), f4_to_fp8(apre1));
            if (kb + 1 < NSTAGE) {
                apre0 = aS[(kb + 1) * 32];
                apre1 = aS[(kb + 1) * 32 + 1];
            }
            // wait current B, single barrier, then refill the drained buffer
            if (buf == 0) { MBARRIER_WAIT_PARITY(sb + SM_MBAR, par[0]); par[0] ^= 1; }
            else          { MBARRIER_WAIT_PARITY(sb + SM_MBAR + 8, par[1]); par[1] ^= 1; }
            __syncthreads();
            if (kb + 1 < NSTAGE && tid == 0) {
                const int nb = (kb + 1) & 1;
                MBARRIER_EXPECT_TX(sb + SM_MBAR + 8 * nb, B_STAGE_BYTES);
                bulk_g2s(sb + SM_B + nb * 65536, bsrc + (kb + 1) * B_STAGE_BYTES,
                         B_STAGE_BYTES, sb + SM_MBAR + 8 * nb);
            }

            #pragma unroll
            for (int ks = 0; ks < 4; ++ks) {      // k32 slice within 128-fp8 stage
                const int cc = ks * 2 + clane;
                uint32_t a0, a1, a2, a3;
                ldmx4(Ab + arow_l * 128 + ((cc ^ (arow_l & 7)) << 4), a0, a1, a2, a3);
                #pragma unroll
                for (int nh = 0; nh < 2; ++nh) {
                    uint32_t b[2][4];
                    #pragma unroll
                    for (int nj = 0; nj < 2; ++nj) {
                        int row = brow_l + nh * 32 + nj * 16;
                        ldmx4(Bb + row * 128 + ((cc ^ (row & 7)) << 4),
                              b[nj][0], b[nj][1], b[nj][2], b[nj][3]);
                    }
                    #pragma unroll
                    for (int n = 0; n < 4; ++n)
                        mma_fp8(acc[nh * 4 + n], a0, a1, a2, a3,
                                b[n >> 1][n & 1], b[n >> 1][2 + (n & 1)]);
                }
            }
        }

        // ---- epilogue 1: per-row approx min over this warp's 64 cols ----
        {
            float v0 = __int_as_float(0x7F800000), v1 = v0;
            #pragma unroll
            for (int n = 0; n < 8; ++n) {
                int col = wc * 64 + n * 8 + tig * 2;
                float c0 = chalf_s[col], c1 = chalf_s[col + 1];
                v0 = fminf(v0, fminf(c0 - acc[n][0], c1 - acc[n][1]));
                v1 = fminf(v1, fminf(c0 - acc[n][2], c1 - acc[n][3]));
            }
            #pragma unroll
            for (int o = 1; o < 4; o <<= 1) {
                v0 = fminf(v0, __shfl_xor_sync(0xffffffffu, v0, o));
                v1 = fminf(v1, __shfl_xor_sync(0xffffffffu, v1, o));
            }
            if (tig == 0) {
                pmin_s[(wr * 16 + gid) * 8 + wc] = v0;
                pmin_s[(wr * 16 + gid + 8) * 8 + wc] = v1;
            }
        }
        __syncthreads();
        if (tid < TM) {
            float v = pmin_s[tid * 8];
            #pragma unroll
            for (int w = 1; w < 8; ++w) v = fminf(v, pmin_s[tid * 8 + w]);
            thr_s[tid] = v + TAU;
        }
        __syncthreads();

        // ---- epilogue 2: collect candidates ----
        #pragma unroll
        for (int n = 0; n < 8; ++n) {
            #pragma unroll
            for (int r = 0; r < 4; ++r) {
                int row = wr * 16 + gid + (r >> 1) * 8;
                int col = wc * 64 + n * 8 + tig * 2 + (r & 1);
                float s = chalf_s[col] - acc[n][r];
                if (s <= thr_s[row]) {
                    int idx = atomicAdd(cnt_s, 1);
                    if (idx < CAP) cand_s[idx] = (row << 16) | col;
                }
            }
        }
        __syncthreads();
        const int ncand = min(cnt_s[0], CAP);

        // ---- epilogue 3: exact fp32 rescore (one warp per candidate) ----
        for (int i = wid; i < ncand; i += 32) {
            int rc = cand_s[i];
            int row = rc >> 16, col = rc & 0xFFFF;
            const float4* e4 = emb4 + (size_t)rowidx_s[row] * 256;
            const float4* c4 = cent4 + ((size_t)m * K_CLUST + col) * 256;
            float d = 0.f;
            #pragma unroll
            for (int q = 0; q < 8; ++q) {
                float4 ea = e4[q * 32 + lane];
                float4 ca = c4[q * 32 + lane];
                d += ea.x * ca.x + ea.y * ca.y + ea.z * ca.z + ea.w * ca.w;
            }
            #pragma unroll
            for (int o = 16; o; o >>= 1) d += __shfl_xor_sync(0xffffffffu, d, o);
            if (lane == 0) {
                float s = chalf_s[col] - d;   // exact fp32 score
                unsigned long long key = ((unsigned long long)fkey(s) << 32) | (unsigned)col;
                atomicMin(&best_s[row], key); // ties -> smaller col (first-min)
            }
        }
        __syncthreads();
        if (tid < TM) code_s[tid] = (int)(unsigned)(best_s[tid] & 0xFFFFFFFFull);
        __syncthreads();

        // ---- epilogue 4: write output rows directly ----
        float4* out4 = reinterpret_cast<float4*>(out);
        for (int idx = tid; idx < TM * 256; idx += NTHREADS) {
            int r = idx >> 8, q = idx & 255;
            if (mt * TM + r < cnt) {
                int frame = rowidx_s[r];
                out4[(size_t)frame * 256 + q] =
                    cent4[((size_t)m * K_CLUST + code_s[r]) * 256 + q];
            }
        }
    }

    // ---- last-finishing block zeroes g_counts for the NEXT call ----
    // Every block read g_counts before incrementing g_done, so zeroing
    // strictly follows all reads. g_done self-resets -> deterministic.
    __syncthreads();
    if (tid == 0) {
        __threadfence();
        int d = atomicAdd(&g_done, 1);
        if (d == (int)gridDim.x - 1) {
            g_done = 0;
            #pragma unroll
            for (int i = 0; i < M_MODELS; ++i) g_counts[i] = 0;
            __threadfence();
        }
    }
}

// ================= launch =================
extern "C" void kernel_launch(void* const* d_in, const int* in_sizes, int n_in,
                              void* d_out, int out_size) {
    const float* emb  = (const float*)d_in[0];
    const float* cent = (const float*)d_in[1];
    const int*   midx = (const int*)d_in[2];
    float* out = (float*)d_out;

    cudaFuncSetAttribute(fused_kernel,
                         cudaFuncAttributeMaxDynamicSharedMemorySize, SMEM_TOTAL);

    prep_kernel<<<(M_MODELS * K_CLUST * 32) / 256, 256>>>(cent, midx);

    // fused launch with programmatic dependent launch (overlaps prep tail)
    cudaLaunchConfig_t cfg = {};
    cfg.gridDim = dim3(M_MODELS * MAXT_G);
    cfg.blockDim = dim3(NTHREADS);
    cfg.dynamicSmemBytes = SMEM_TOTAL;
    cfg.stream = 0;
    cudaLaunchAttribute at[1];
    at[0].id = cudaLaunchAttributeProgrammaticStreamSerialization;
    at[0].val.programmaticStreamSerializationAllowed = 1;
    cfg.attrs = at;
    cfg.numAttrs = 1;
    cudaLaunchKernelEx(&cfg, fused_kernel, emb, cent, out);
}